// round 6
// baseline (speedup 1.0000x reference)
#include <cuda_runtime.h>
#include <cuda_bf16.h>

#define BQ   256
#define TT   512
#define EE   128
#define HH   256
#define NB   32      // batches per group
#define NGRP 8       // groups per direction
#define NCTA 8       // cluster CTAs per group (j-split)
#define ROWS 96      // gate rows per CTA
#define NTH  384     // 12 warps, 3 per SMSP (balanced)
#define KTOT 384
#define KIN  128
#define KPAD 388     // weight row pitch (floats): 1552B -> 16B bank offset/row
#define PREP 36      // preact row pitch (floats): 144B, 16B aligned

typedef unsigned long long u64;

// ---------------- device scratch ----------------
__device__ float4 g_wprep4[(2 * NCTA * ROWS * KPAD) / 4];  // [dir][cta][row][kpad]
__device__ float  g_fc1T[512 * 128];
__device__ float  g_fc2T[128 * 64];
__device__ float  g_h[BQ * 2 * HH];
__device__ int    g_order[BQ];
__device__ float  g_hx[2 * NGRP * 2 * HH * NB];            // [dir][grp][parity][col][nb]

// ---------------- helpers ----------------
__device__ __forceinline__ u64 ffma2(u64 a, u64 b, u64 c) {
    u64 d; asm("fma.rn.f32x2 %0, %1, %2, %3;" : "=l"(d) : "l"(a), "l"(b), "l"(c)); return d;
}
__device__ __forceinline__ u64 pack2(float lo, float hi) {
    u64 d; asm("mov.b64 %0, {%1, %2};" : "=l"(d) : "f"(lo), "f"(hi)); return d;
}
__device__ __forceinline__ float sigf(float x) { return __fdividef(1.0f, 1.0f + __expf(-x)); }
__device__ __forceinline__ float tanhfast(float x) { return 1.0f - __fdividef(2.0f, __expf(2.0f * x) + 1.0f); }

#define CLUSTER_ARRIVE() asm volatile("barrier.cluster.arrive.aligned;" ::: "memory")
#define CLUSTER_WAIT()   asm volatile("barrier.cluster.wait.aligned;"  ::: "memory")

// SMEM layout (bytes)
#define OFF_W    0                                  // [96][388] f32 : 148992
#define OFF_XIN  148992                             // [384][32] f32 : 49152
#define OFF_PX   198144                             // [96][36]  f32 : 13824
#define OFF_PH   211968                             // [96][36]  f32 : 13824
#define OFF_OB   225792                             // int[32]
#define OFF_LEN  225920                             // int[32]
#define SMEM_SZ  226048

// ---------------- prep ----------------
__global__ void prep_kernel(const float* __restrict__ wihf, const float* __restrict__ whhf,
                            const float* __restrict__ wihb, const float* __restrict__ whhb,
                            const float* __restrict__ fc1w, const float* __restrict__ fc2w) {
    int idx = blockIdx.x * blockDim.x + threadIdx.x;
    const int NW = 2 * NCTA * ROWS * KPAD;              // 595968
    const int B1 = NW, B2 = B1 + 512 * 128, B3 = B2 + 128 * 64;
    if (idx < NW) {
        int kpad = idx % KPAD;
        int row  = (idx / KPAD) % ROWS;
        int cta  = (idx / (KPAD * ROWS)) % NCTA;
        int dir  = idx / (KPAD * ROWS * NCTA);
        const float* wih = dir ? wihb : wihf;
        const float* whh = dir ? whhb : whhf;
        int grow = (row >> 5) * HH + cta * 32 + (row & 31);   // gate*256 + col
        float v = 0.0f;
        if (kpad < KIN)       v = wih[grow * EE + kpad];
        else if (kpad < KTOT) v = whh[grow * HH + (kpad - KIN)];
        ((float*)g_wprep4)[idx] = v;
    } else if (idx < B2) {
        int o = idx - B1; int k = o / 128, i = o % 128;
        g_fc1T[o] = fc1w[i * 512 + k];
    } else if (idx < B3) {
        int o = idx - B2; int k = o / 64, i = o % 64;
        g_fc2T[o] = fc2w[i * 128 + k];
    }
}

// ---------------- sort batch by length (ascending bitonic) ----------------
__global__ void sort_kernel(const int* __restrict__ lengths) {
    __shared__ int key[BQ], val[BQ];
    unsigned t = threadIdx.x;
    key[t] = lengths[t]; val[t] = (int)t;
    __syncthreads();
    for (unsigned size = 2; size <= BQ; size <<= 1) {
        for (unsigned stride = size >> 1; stride > 0; stride >>= 1) {
            __syncthreads();
            unsigned j = t ^ stride;
            if (j > t) {
                bool up = ((t & size) == 0);
                int kt = key[t], kj = key[j];
                if ((kt > kj) == up) {
                    key[t] = kj; key[j] = kt;
                    int vt = val[t]; val[t] = val[j]; val[j] = vt;
                }
            }
        }
    }
    __syncthreads();
    g_order[t] = val[t];
}

// ---------------- GRU: cluster of 8 CTAs per (dir, group) ----------------
__global__ __launch_bounds__(NTH, 1) __cluster_dims__(NCTA, 1, 1)
void gru_kernel(const int* __restrict__ x, const int* __restrict__ lengths,
                const float* __restrict__ emb,
                const float* __restrict__ bih_f, const float* __restrict__ bhh_f,
                const float* __restrict__ bih_b, const float* __restrict__ bhh_b) {

    const int cta = blockIdx.x, grp = blockIdx.y, dir = blockIdx.z;
    const int tid = threadIdx.x;
    const int row = tid >> 2;            // 0..95
    const int nb8 = (tid & 3) * 8;       // batch base (8 per thread)

    extern __shared__ __align__(16) char sm[];
    float* w_s  = (float*)(sm + OFF_W);      // [96][388]
    float* xin  = (float*)(sm + OFF_XIN);    // [384][32]
    float* preX = (float*)(sm + OFF_PX);     // [96][36]
    float* preH = (float*)(sm + OFF_PH);     // [96][36]
    int*   ob_s  = (int*)(sm + OFF_OB);
    int*   len_s = (int*)(sm + OFF_LEN);

    if (tid < NB) {
        int o = g_order[grp * NB + tid];
        ob_s[tid] = o;
        len_s[tid] = lengths[o];
    }
    // weights -> SMEM (one-time)
    {
        const float4* wg = g_wprep4 + (size_t)(dir * NCTA + cta) * (ROWS * KPAD / 4);
        float4* wd = (float4*)w_s;
        for (int i = tid; i < ROWS * KPAD / 4; i += NTH) wd[i] = wg[i];
    }
    // zero hidden region of xin
    for (int i = tid; i < HH * NB; i += NTH) xin[KIN * NB + i] = 0.0f;
    __syncthreads();

    const int M = len_s[NB - 1];
    const int grow = (row >> 5) * HH + cta * 32 + (row & 31);
    const float* bihp = dir ? bih_b : bih_f;
    const float* bhhp = dir ? bhh_b : bhh_f;
    const u64 bX = pack2(bihp[grow], bihp[grow]);
    const u64 bH = pack2(bhhp[grow], bhhp[grow]);
    float* hx0 = g_hx + (size_t)(dir * NGRP + grp) * 2 * HH * NB;
    const float* wr = w_s + row * KPAD;

    // prologue: gather embedding for step 0 (layout xin[k][nb])
    {
        int t0 = dir ? (M - 1) : 0;
        for (int i = tid; i < 1024; i += NTH) {
            int nb = i & 31, k4 = i >> 5;
            int tok = x[ob_s[nb] * TT + t0];
            float4 v = *(const float4*)(emb + (size_t)tok * EE + k4 * 4);
            xin[(k4 * 4 + 0) * NB + nb] = v.x;
            xin[(k4 * 4 + 1) * NB + nb] = v.y;
            xin[(k4 * 4 + 2) * NB + nb] = v.z;
            xin[(k4 * 4 + 3) * NB + nb] = v.w;
        }
    }
    __syncthreads();

    for (int s = 0; s < M; s++) {
        // ---- A: input projection k=0..127 ----
        {
            u64 a0 = bX, a1 = bX, a2 = bX, a3 = bX;
#pragma unroll 4
            for (int k = 0; k < KIN; k += 4) {
                float4 w4 = *(const float4*)(wr + k);
                const float* wk = (const float*)&w4;
#pragma unroll
                for (int kk = 0; kk < 4; kk++) {
                    u64 wd = pack2(wk[kk], wk[kk]);
                    ulonglong2 xv = *(const ulonglong2*)(xin + (k + kk) * NB + nb8);
                    ulonglong2 yv = *(const ulonglong2*)(xin + (k + kk) * NB + nb8 + 4);
                    a0 = ffma2(wd, xv.x, a0); a1 = ffma2(wd, xv.y, a1);
                    a2 = ffma2(wd, yv.x, a2); a3 = ffma2(wd, yv.y, a3);
                }
            }
            ulonglong2* p = (ulonglong2*)(preX + row * PREP + nb8);
            p[0] = make_ulonglong2(a0, a1); p[1] = make_ulonglong2(a2, a3);
        }
        __syncthreads();

        // ---- gather embedding for next step (independent of barrier) ----
        if (s + 1 < M) {
            int tn = dir ? (M - 2 - s) : (s + 1);
            for (int i = tid; i < 1024; i += NTH) {
                int nb = i & 31, k4 = i >> 5;
                int tok = x[ob_s[nb] * TT + tn];
                float4 v = *(const float4*)(emb + (size_t)tok * EE + k4 * 4);
                xin[(k4 * 4 + 0) * NB + nb] = v.x;
                xin[(k4 * 4 + 1) * NB + nb] = v.y;
                xin[(k4 * 4 + 2) * NB + nb] = v.z;
                xin[(k4 * 4 + 3) * NB + nb] = v.w;
            }
        }

        // ---- wait for peers' h^s, then copy into xin hidden region ----
        if (s > 0) {
            CLUSTER_WAIT();
            const float4* src = (const float4*)(hx0 + (size_t)(s & 1) * HH * NB);
            float4* dst = (float4*)(xin + KIN * NB);
            for (int i = tid; i < HH * NB / 4; i += NTH) dst[i] = __ldcg(src + i);
        }
        __syncthreads();

        // ---- D: hidden projection k=128..383 ----
        {
            u64 a0 = bH, a1 = bH, a2 = bH, a3 = bH;
#pragma unroll 4
            for (int k = KIN; k < KTOT; k += 4) {
                float4 w4 = *(const float4*)(wr + k);
                const float* wk = (const float*)&w4;
#pragma unroll
                for (int kk = 0; kk < 4; kk++) {
                    u64 wd = pack2(wk[kk], wk[kk]);
                    ulonglong2 xv = *(const ulonglong2*)(xin + (k + kk) * NB + nb8);
                    ulonglong2 yv = *(const ulonglong2*)(xin + (k + kk) * NB + nb8 + 4);
                    a0 = ffma2(wd, xv.x, a0); a1 = ffma2(wd, xv.y, a1);
                    a2 = ffma2(wd, yv.x, a2); a3 = ffma2(wd, yv.y, a3);
                }
            }
            ulonglong2* p = (ulonglong2*)(preH + row * PREP + nb8);
            p[0] = make_ulonglong2(a0, a1); p[1] = make_ulonglong2(a2, a3);
        }
        __syncthreads();

        // ---- E: gates + combine + publish ----
        {
            const int t = dir ? (M - 1 - s) : s;
            float* hw = hx0 + (size_t)((s + 1) & 1) * HH * NB + cta * 32 * NB;
            for (int idx = tid; idx < 32 * NB; idx += NTH) {
                int col = idx >> 5, nb = idx & 31;
                float xr = preX[col * PREP + nb],        hr = preH[col * PREP + nb];
                float xz = preX[(32 + col) * PREP + nb], hz = preH[(32 + col) * PREP + nb];
                float xn = preX[(64 + col) * PREP + nb], hn = preH[(64 + col) * PREP + nb];
                float r  = sigf(xr + hr);
                float z  = sigf(xz + hz);
                float nv = tanhfast(xn + r * hn);
                float hold = xin[(KIN + cta * 32 + col) * NB + nb];
                float hnew = (t < len_s[nb]) ? ((1.0f - z) * nv + z * hold) : hold;
                if (s + 1 < M) {
                    __stcg(hw + col * NB + nb, hnew);
                } else {
                    g_h[(size_t)ob_s[nb] * (2 * HH) + dir * HH + cta * 32 + col] = hnew;
                }
            }
        }
        if (s + 1 < M) CLUSTER_ARRIVE();   // release: publishes h^{s+1} to cluster
        __syncthreads();
    }
}

// ---------------- head: fc1 + relu + fc2 + L2 normalize ----------------
__global__ __launch_bounds__(128) void head_kernel(const float* __restrict__ fc1_b,
                                                   const float* __restrict__ fc2_b,
                                                   float* __restrict__ out) {
    __shared__ float hsm[512];
    __shared__ float hid[128];
    __shared__ float osm[64];
    __shared__ float inv_s;
    const int b = blockIdx.x, t = threadIdx.x;

    ((float4*)hsm)[t] = ((const float4*)(g_h + (size_t)b * 512))[t];
    __syncthreads();

    float acc = fc1_b[t];
#pragma unroll 8
    for (int k = 0; k < 512; k++) acc += g_fc1T[k * 128 + t] * hsm[k];
    hid[t] = fmaxf(acc, 0.0f);
    __syncthreads();

    if (t < 64) {
        float a = fc2_b[t];
#pragma unroll 8
        for (int k = 0; k < 128; k++) a += g_fc2T[k * 64 + t] * hid[k];
        osm[t] = a;
    }
    __syncthreads();
    if (t == 0) {
        float ss = 0.0f;
        for (int o = 0; o < 64; o++) ss += osm[o] * osm[o];
        inv_s = 1.0f / fmaxf(sqrtf(ss), 1e-12f);
    }
    __syncthreads();
    if (t < 64) out[b * 64 + t] = osm[t] * inv_s;
}

// ---------------- launch ----------------
extern "C" void kernel_launch(void* const* d_in, const int* in_sizes, int n_in,
                              void* d_out, int out_size) {
    const int*   x        = (const int*)d_in[0];
    const int*   lengths  = (const int*)d_in[1];
    const float* emb      = (const float*)d_in[2];
    const float* w_ih_f   = (const float*)d_in[3];
    const float* w_hh_f   = (const float*)d_in[4];
    const float* b_ih_f   = (const float*)d_in[5];
    const float* b_hh_f   = (const float*)d_in[6];
    const float* w_ih_b   = (const float*)d_in[7];
    const float* w_hh_b   = (const float*)d_in[8];
    const float* b_ih_b   = (const float*)d_in[9];
    const float* b_hh_b   = (const float*)d_in[10];
    const float* fc1_w    = (const float*)d_in[11];
    const float* fc1_b    = (const float*)d_in[12];
    const float* fc2_w    = (const float*)d_in[13];
    const float* fc2_b    = (const float*)d_in[14];
    float* out = (float*)d_out;

    static bool attr_set = false;
    if (!attr_set) {
        cudaFuncSetAttribute(gru_kernel, cudaFuncAttributeMaxDynamicSharedMemorySize, SMEM_SZ);
        attr_set = true;
    }

    const int total = 2 * NCTA * ROWS * KPAD + 512 * 128 + 128 * 64;
    prep_kernel<<<(total + 255) / 256, 256>>>(w_ih_f, w_hh_f, w_ih_b, w_hh_b, fc1_w, fc2_w);
    sort_kernel<<<1, BQ>>>(lengths);
    dim3 gg(NCTA, NGRP, 2);
    gru_kernel<<<gg, NTH, SMEM_SZ>>>(x, lengths, emb, b_ih_f, b_hh_f, b_ih_b, b_hh_b);
    head_kernel<<<BQ, 128>>>(fc1_b, fc2_b, out);
}